// round 1
// baseline (speedup 1.0000x reference)
#include <cuda_runtime.h>
#include <math.h>

#define NB 32
#define NT 36
#define NN 10000
#define NF 3
#define NH 10
#define NR 20
#define PRED_ELEMS (NB * NH * NN)   // 3,200,000

// ---------------- device scratch (no allocations allowed) ----------------
__device__ float g_time_mean[NB * NN];   // [B, N]
__device__ float g_rsum[NB * NR];        // per (b, r) sum of valid time_means
__device__ float g_rcnt[NB * NR];        // per (b, r) count of valid time_means
__device__ float g_g1;                   // global nanmean of pred_speed
__device__ int   g_is64;                 // cluster_id stored as int64?

// ---------------- K0: zero accumulators + detect cluster_id dtype ----------------
__global__ void k0_init(const int* __restrict__ cid32) {
    for (int i = threadIdx.x; i < NB * NR; i += blockDim.x) {
        g_rsum[i] = 0.0f;
        g_rcnt[i] = 0.0f;
    }
    __shared__ int s_bad;
    if (threadIdx.x == 0) s_bad = 0;
    __syncthreads();
    // If data is int64 (values 0..19), every odd 32-bit word is 0.
    // Scan only first NN/2 candidates so reads stay in-bounds for the
    // int32 case (indices <= 9999 < 10000).
    int bad = 0;
    for (int i = threadIdx.x; i < NN / 2; i += blockDim.x) {
        if (cid32[2 * i + 1] != 0) bad = 1;
    }
    if (bad) atomicOr(&s_bad, 1);
    __syncthreads();
    if (threadIdx.x == 0) g_is64 = (s_bad == 0) ? 1 : 0;
}

// ---------------- K1: time-mean over T + region accumulation ----------------
// grid: (ceil(NN/256), NB), block: 256
__global__ void __launch_bounds__(256) k1_time_mean(
    const float* __restrict__ seq, const int* __restrict__ cid32) {
    const int b = blockIdx.y;
    const int n = blockIdx.x * blockDim.x + threadIdx.x;

    __shared__ float s_rsum[NR];
    __shared__ float s_rcnt[NR];
    if (threadIdx.x < NR) {
        s_rsum[threadIdx.x] = 0.0f;
        s_rcnt[threadIdx.x] = 0.0f;
    }
    __syncthreads();

    if (n < NN) {
        const float* base = seq + (size_t)b * NT * NN * NF + (size_t)n * NF;
        float s = 0.0f, c = 0.0f;
#pragma unroll
        for (int t = 0; t < NT; t++) {
            float x = __ldg(base + (size_t)t * (NN * NF));
            if (x == x) { s += x; c += 1.0f; }
        }
        float tm = s / c;                 // 0/0 -> NaN when node all-NaN
        g_time_mean[b * NN + n] = tm;

        int r = g_is64 ? cid32[2 * n] : cid32[n];
        if (tm == tm) {
            atomicAdd(&s_rsum[r], tm);
            atomicAdd(&s_rcnt[r], 1.0f);
        }
    }
    __syncthreads();
    if (threadIdx.x < NR) {
        atomicAdd(&g_rsum[b * NR + threadIdx.x], s_rsum[threadIdx.x]);
    } else if (threadIdx.x < 2 * NR) {
        int r = threadIdx.x - NR;
        atomicAdd(&g_rcnt[b * NR + r], s_rcnt[r]);
    }
}

// ---------------- K2: finalize regional, g1, g2; write out_regional ----------------
// 1 block, 640 threads (one per (b, r))
__global__ void __launch_bounds__(640) k2_finalize(float* __restrict__ out) {
    const int i = threadIdx.x;          // 0..639
    const int b = i / NR;
    const int r = i % NR;

    float rs = g_rsum[i];
    float rc = g_rcnt[i];
    float reg = rs / rc;                // NaN if region empty for this batch
    bool rv = (reg == reg);

    // Reduce 4 quantities over 640 threads:
    // v0 = total valid sum, v1 = total valid count (-> g1)
    // v2 = sum of valid regional, v3 = count of valid regional (-> g2)
    float v0 = rs, v1 = rc;
    float v2 = rv ? reg : 0.0f, v3 = rv ? 1.0f : 0.0f;
#pragma unroll
    for (int o = 16; o > 0; o >>= 1) {
        v0 += __shfl_down_sync(0xFFFFFFFFu, v0, o);
        v1 += __shfl_down_sync(0xFFFFFFFFu, v1, o);
        v2 += __shfl_down_sync(0xFFFFFFFFu, v2, o);
        v3 += __shfl_down_sync(0xFFFFFFFFu, v3, o);
    }
    __shared__ float sw[20][4];
    const int w = i >> 5, l = i & 31;
    if (l == 0) { sw[w][0] = v0; sw[w][1] = v1; sw[w][2] = v2; sw[w][3] = v3; }
    __syncthreads();

    __shared__ float s_g1, s_g2;
    if (w == 0) {
        float a0 = (l < 20) ? sw[l][0] : 0.0f;
        float a1 = (l < 20) ? sw[l][1] : 0.0f;
        float a2 = (l < 20) ? sw[l][2] : 0.0f;
        float a3 = (l < 20) ? sw[l][3] : 0.0f;
#pragma unroll
        for (int o = 16; o > 0; o >>= 1) {
            a0 += __shfl_down_sync(0xFFFFFFFFu, a0, o);
            a1 += __shfl_down_sync(0xFFFFFFFFu, a1, o);
            a2 += __shfl_down_sync(0xFFFFFFFFu, a2, o);
            a3 += __shfl_down_sync(0xFFFFFFFFu, a3, o);
        }
        if (l == 0) {
            float g1v = a0 / a1;
            float g2v = a2 / a3;
            s_g1 = g1v;
            s_g2 = g2v;
            g_g1 = g1v;
        }
    }
    __syncthreads();

    float g2 = s_g2;
    float val = rv ? reg : g2;
    float* outR = out + PRED_ELEMS;     // regional output follows pred output
#pragma unroll
    for (int h = 0; h < NH; h++) {
        outR[(b * NH + h) * NR + r] = val;
    }
}

// ---------------- K3: broadcast pred output (NaN -> g1) ----------------
// grid: (ceil(NN/256), NB), block: 256
__global__ void __launch_bounds__(256) k3_pred(float* __restrict__ out) {
    const int b = blockIdx.y;
    const int n = blockIdx.x * blockDim.x + threadIdx.x;
    if (n >= NN) return;
    float tm = g_time_mean[b * NN + n];
    float v = (tm == tm) ? tm : g_g1;
#pragma unroll
    for (int h = 0; h < NH; h++) {
        out[(size_t)(b * NH + h) * NN + n] = v;
    }
}

// ---------------- launcher ----------------
extern "C" void kernel_launch(void* const* d_in, const int* in_sizes, int n_in,
                              void* d_out, int out_size) {
    const float* seq = (const float*)d_in[0];
    const int* cid = (const int*)d_in[1];   // int32 or int64 -- probed at runtime
    float* out = (float*)d_out;

    k0_init<<<1, 256>>>(cid);

    dim3 grid((NN + 255) / 256, NB);
    k1_time_mean<<<grid, 256>>>(seq, cid);
    k2_finalize<<<1, 640>>>(out);
    k3_pred<<<grid, 256>>>(out);
}